// round 6
// baseline (speedup 1.0000x reference)
#include <cuda_runtime.h>
#include <cstdint>

// NLinear via mma.sync tf32 (base sm_100 target).
// R6: A staged via LDG->cvt->STS into k-interleaved layout (CVT once per element,
// hot-loop A = LDS.64 only). B stays cp.async (3 stages) with in-loop cvt (x2 dup).
// out[b,n,o] = sum_i x[b,n,i]*W[n,i,o] + bias[n,o]

static constexpr int N_POS = 128;
static constexpr int D_IN  = 512;
static constexpr int D_OUT = 512;
static constexpr int BATCH = 256;
static constexpr int XSTR  = N_POS * D_IN;   // 65536
static constexpr int WSTR  = D_IN * D_OUT;   // 262144

static constexpr int BM = 128;
static constexpr int BN = 128;
static constexpr int BK = 32;
static constexpr int KITERS = D_IN / BK;     // 16

// A interleaved smem: [m][k-interleaved], row stride 40 floats, double buffered.
static constexpr int ASTR_I = 40;
static constexpr int A_ELE  = BM * ASTR_I;           // 5120
// B raw smem: [k][n], row stride 132, 3 stages.
static constexpr int BSTR = 132;
static constexpr int B_ELE = BK * BSTR;              // 4224
static constexpr int A_REGION = 2 * A_ELE;           // 10240
static constexpr int SMEM_ELE = A_REGION + 3 * B_ELE;    // 22912
static constexpr int SMEM_BYTES = SMEM_ELE * 4;          // 91648

__device__ __forceinline__ void cp16(float* dst_smem, const float* src) {
    uint32_t d = (uint32_t)__cvta_generic_to_shared(dst_smem);
    asm volatile("cp.async.cg.shared.global [%0], [%1], 16;" :: "r"(d), "l"(src));
}
__device__ __forceinline__ void cp_commit() {
    asm volatile("cp.async.commit_group;" ::: "memory");
}
template <int N>
__device__ __forceinline__ void cp_wait() {
    asm volatile("cp.async.wait_group %0;" :: "n"(N) : "memory");
}
__device__ __forceinline__ uint32_t f2tf32(float f) {
    uint32_t r;
    asm("cvt.rna.tf32.f32 %0, %1;" : "=r"(r) : "f"(f));
    return r;
}
__device__ __forceinline__ void mma_tf32(float c[4],
                                         const uint32_t a[4],
                                         const uint32_t b[2]) {
    asm volatile(
        "mma.sync.aligned.m16n8k8.row.col.f32.tf32.tf32.f32 "
        "{%0,%1,%2,%3}, {%4,%5,%6,%7}, {%8,%9}, {%0,%1,%2,%3};"
        : "+f"(c[0]), "+f"(c[1]), "+f"(c[2]), "+f"(c[3])
        : "r"(a[0]), "r"(a[1]), "r"(a[2]), "r"(a[3]), "r"(b[0]), "r"(b[1]));
}

// ---- A staging: each thread handles half a row (16 k-values) ----
__device__ __forceinline__ void ldgA(float areg[16], const float* xrow, int k0) {
    #pragma unroll
    for (int q = 0; q < 4; q++)
        *(float4*)(areg + q * 4) = *(const float4*)(xrow + k0 + q * 4);
}
// cvt + store into k-interleaved layout: within k8 block, element kb at pos
// 2*(kb&3) + (kb>>2); pairs (jb, jb+4) -> one 64-bit store at offset 2*jb.
__device__ __forceinline__ void stsA(float* Abuf, const float areg[16],
                                     int m, int khalf) {
    float* row = Abuf + m * ASTR_I + khalf * 16;
    #pragma unroll
    for (int blk = 0; blk < 2; blk++) {
        #pragma unroll
        for (int jb = 0; jb < 4; jb++) {
            uint2 u;
            u.x = f2tf32(areg[blk * 8 + jb]);
            u.y = f2tf32(areg[blk * 8 + jb + 4]);
            *(uint2*)(row + blk * 8 + 2 * jb) = u;
        }
    }
}

__device__ __forceinline__ void cpB(float* Bst, const float* wb, int k0, int tid) {
    #pragma unroll
    for (int j = 0; j < 4; j++) {            // 32 x 128 = 1024 x 16B
        int c  = tid + j * 256;
        int kr = c >> 5;
        int nc = c & 31;
        cp16(Bst + kr * BSTR + nc * 4, wb + (size_t)(k0 + kr) * D_OUT + nc * 4);
    }
    cp_commit();
}

__global__ __launch_bounds__(256, 2)
void nlinear_mma_kernel(const float* __restrict__ x,
                        const float* __restrict__ w,
                        const float* __restrict__ bias,
                        float* __restrict__ out)
{
    extern __shared__ float sm[];

    const int tid = threadIdx.x;
    const int wid = tid >> 5;
    const int lid = tid & 31;
    const int g   = lid >> 2;   // 0..7
    const int t   = lid & 3;    // 0..3

    const int n     = blockIdx.z;
    const int obase = blockIdx.x * BN;
    const int mbase = blockIdx.y * BM;

    // warp grid 2 (M) x 4 (N): warp tile 64 x 32
    const int wm0 = (wid & 1) * 64;
    const int wn0 = (wid >> 1) * 32;

    const float* xb = x + (size_t)mbase * XSTR + (size_t)n * D_IN;
    const float* wb = w + (size_t)n * WSTR + obase;

    // A staging assignment: m = tid>>1, khalf = tid&1
    const int am    = tid >> 1;
    const int akh   = tid & 1;
    const float* xrow = xb + (size_t)am * XSTR + akh * 16;

    float* Ab[2] = { sm, sm + A_ELE };
    float* Bb[3] = { sm + A_REGION, sm + A_REGION + B_ELE, sm + A_REGION + 2 * B_ELE };

    // hoisted hot-loop bases
    const int a_base0 = (wm0 + g) * ASTR_I;          // row g
    const int a_base8 = (wm0 + g + 8) * ASTR_I;      // row g+8
    const int b_off   = t * BSTR + wn0 + g;

    float acc[4][4][4];
    #pragma unroll
    for (int mt = 0; mt < 4; mt++)
        #pragma unroll
        for (int nt = 0; nt < 4; nt++)
            #pragma unroll
            for (int q = 0; q < 4; q++)
                acc[mt][nt][q] = 0.0f;

    float areg[16];

    // ---- Prologue: A0 staged, A1 in regs; B0, B1 in flight ----
    ldgA(areg, xrow, 0);
    cpB(Bb[0], wb, 0, tid);                  // group 0
    stsA(Ab[0], areg, am, akh);
    ldgA(areg, xrow, BK);                    // chunk 1 in regs
    cpB(Bb[1], wb, BK, tid);                 // group 1
    cp_wait<1>();                            // B0 done
    __syncthreads();                         // A0 visible

    for (int it = 0; it < KITERS; ++it) {
        // B prefetch depth 2 (buffer (it+2)%3 free since barrier end of it-1)
        if (it + 2 < KITERS) cpB(Bb[(it + 2) % 3], wb, (it + 2) * BK, tid);
        else                 cp_commit();    // keep group numbering

        const float* As = Ab[it & 1];
        const float* Bs = Bb[it % 3];

        #pragma unroll
        for (int ks = 0; ks < 4; ks++) {
            const int kk = ks * 8;
            uint32_t a[4][4];
            uint32_t b[4][2];
            #pragma unroll
            for (int mt = 0; mt < 4; mt++) {
                uint2 u0 = *(const uint2*)(As + a_base0 + mt * 16 * ASTR_I + kk + 2 * t);
                uint2 u1 = *(const uint2*)(As + a_base8 + mt * 16 * ASTR_I + kk + 2 * t);
                a[mt][0] = u0.x;  // (g,   t)
                a[mt][1] = u1.x;  // (g+8, t)
                a[mt][2] = u0.y;  // (g,   t+4)
                a[mt][3] = u1.y;  // (g+8, t+4)
            }
            #pragma unroll
            for (int nt = 0; nt < 4; nt++) {
                const float* bp = Bs + b_off + kk * BSTR + 8 * nt;
                b[nt][0] = f2tf32(bp[0]);
                b[nt][1] = f2tf32(bp[4 * BSTR]);
            }
            #pragma unroll
            for (int mt = 0; mt < 4; mt++)
                #pragma unroll
                for (int nt = 0; nt < 4; nt++)
                    mma_tf32(acc[mt][nt], a[mt], b[nt]);
        }

        // Stage A(it+1) from regs (buffer was last read in it-1; barrier covers)
        if (it + 1 < KITERS) stsA(Ab[(it + 1) & 1], areg, am, akh);
        // Fetch A(it+2) into regs — hidden behind next iteration's compute
        if (it + 2 < KITERS) ldgA(areg, xrow, (it + 2) * BK);

        cp_wait<1>();        // B(it+1) landed
        __syncthreads();     // publish A(it+1); retire reads of old buffers
    }

    // ---- Epilogue: bias + store ----
    const float* brow = bias + (size_t)n * D_OUT + obase;
    #pragma unroll
    for (int mt = 0; mt < 4; mt++) {
        const int r0 = mbase + wm0 + 16 * mt + g;
        float* o0 = out + (size_t)r0 * XSTR + (size_t)n * D_OUT + obase;
        float* o1 = o0 + (size_t)8 * XSTR;
        #pragma unroll
        for (int nt = 0; nt < 4; nt++) {
            const int col = wn0 + 8 * nt + 2 * t;
            float2 bv = *(const float2*)(brow + col);
            float2 v0, v1;
            v0.x = acc[mt][nt][0] + bv.x;
            v0.y = acc[mt][nt][1] + bv.y;
            v1.x = acc[mt][nt][2] + bv.x;
            v1.y = acc[mt][nt][3] + bv.y;
            *(float2*)(o0 + col) = v0;
            *(float2*)(o1 + col) = v1;
        }
    }
}

extern "C" void kernel_launch(void* const* d_in, const int* in_sizes, int n_in,
                              void* d_out, int out_size)
{
    const float* x    = (const float*)d_in[0];
    const float* w    = (const float*)d_in[1];
    const float* bias = (const float*)d_in[2];
    float* out        = (float*)d_out;

    cudaFuncSetAttribute(nlinear_mma_kernel,
                         cudaFuncAttributeMaxDynamicSharedMemorySize, SMEM_BYTES);

    dim3 grid(D_OUT / BN, BATCH / BM, N_POS);   // (4, 2, 128)
    dim3 block(256);
    nlinear_mma_kernel<<<grid, block, SMEM_BYTES>>>(x, w, bias, out);
}

// round 7
// speedup vs baseline: 1.3677x; 1.3677x over previous
#include <cuda_runtime.h>
#include <cstdint>

// NLinear via mma.sync tf32 (base sm_100 target).
// R7: R3 skeleton + conflict-free B stride (136) + 3-stage cp.async +
// register double-buffered fragments (CUTLASS sm80 multistage style), occ 1.
// out[b,n,o] = sum_i x[b,n,i]*W[n,i,o] + bias[n,o]

static constexpr int N_POS = 128;
static constexpr int D_IN  = 512;
static constexpr int D_OUT = 512;
static constexpr int BATCH = 256;
static constexpr int XSTR  = N_POS * D_IN;   // 65536
static constexpr int WSTR  = D_IN * D_OUT;   // 262144

static constexpr int BM = 128;
static constexpr int BN = 128;
static constexpr int BK = 32;
static constexpr int KITERS = D_IN / BK;     // 16
static constexpr int NSTAGE = 3;

static constexpr int ASTR = 36;              // A bank = 4g+t  (all 32 distinct)
static constexpr int BSTR = 136;             // B bank = 8t+g  (all 32 distinct)
static constexpr int A_ELE = BM * ASTR;      // 4608
static constexpr int B_ELE = BK * BSTR;      // 4352
static constexpr int STAGE = A_ELE + B_ELE;  // 8960 floats
static constexpr int SMEM_BYTES = NSTAGE * STAGE * 4;  // 107520

__device__ __forceinline__ void cp16(float* dst_smem, const float* src) {
    uint32_t d = (uint32_t)__cvta_generic_to_shared(dst_smem);
    asm volatile("cp.async.cg.shared.global [%0], [%1], 16;" :: "r"(d), "l"(src));
}
__device__ __forceinline__ void cp_commit() {
    asm volatile("cp.async.commit_group;" ::: "memory");
}
template <int N>
__device__ __forceinline__ void cp_wait() {
    asm volatile("cp.async.wait_group %0;" :: "n"(N) : "memory");
}
__device__ __forceinline__ uint32_t f2tf32(float f) {
    uint32_t r;
    asm("cvt.rna.tf32.f32 %0, %1;" : "=r"(r) : "f"(f));
    return r;
}
__device__ __forceinline__ void mma_tf32(float c[4],
                                         const uint32_t a[4],
                                         const uint32_t b[2]) {
    asm volatile(
        "mma.sync.aligned.m16n8k8.row.col.f32.tf32.tf32.f32 "
        "{%0,%1,%2,%3}, {%4,%5,%6,%7}, {%8,%9}, {%0,%1,%2,%3};"
        : "+f"(c[0]), "+f"(c[1]), "+f"(c[2]), "+f"(c[3])
        : "r"(a[0]), "r"(a[1]), "r"(a[2]), "r"(a[3]), "r"(b[0]), "r"(b[1]));
}

__device__ __forceinline__ void prefetch_stage(float* stage_base,
                                               const float* xb, const float* wb,
                                               int k0, int tid)
{
    float* As = stage_base;
    float* Bs = stage_base + A_ELE;
    #pragma unroll
    for (int j = 0; j < 4; j++) {            // A: 128 x 32 = 1024 x 16B
        int c  = tid + j * 256;
        int m  = c >> 3;
        int kc = c & 7;
        cp16(As + m * ASTR + kc * 4, xb + (size_t)m * XSTR + k0 + kc * 4);
    }
    #pragma unroll
    for (int j = 0; j < 4; j++) {            // B: 32 x 128 = 1024 x 16B
        int c  = tid + j * 256;
        int kr = c >> 5;
        int nc = c & 31;
        cp16(Bs + kr * BSTR + nc * 4, wb + (size_t)(k0 + kr) * D_OUT + nc * 4);
    }
    cp_commit();
}

__device__ __forceinline__ void load_frags(uint32_t a[4][4], uint32_t b[4][2],
                                           const float* As, const float* Bs,
                                           int a_off, int b_off, int kk)
{
    #pragma unroll
    for (int mt = 0; mt < 4; mt++) {
        const float* ap = As + a_off + mt * 16 * ASTR + kk;
        a[mt][0] = f2tf32(ap[0]);
        a[mt][1] = f2tf32(ap[8 * ASTR]);
        a[mt][2] = f2tf32(ap[4]);
        a[mt][3] = f2tf32(ap[8 * ASTR + 4]);
    }
    #pragma unroll
    for (int nt = 0; nt < 4; nt++) {
        const float* bp = Bs + b_off + kk * BSTR + 8 * nt;
        b[nt][0] = f2tf32(bp[0]);
        b[nt][1] = f2tf32(bp[4 * BSTR]);
    }
}

__global__ __launch_bounds__(256, 1)
void nlinear_mma_kernel(const float* __restrict__ x,
                        const float* __restrict__ w,
                        const float* __restrict__ bias,
                        float* __restrict__ out)
{
    extern __shared__ float sm[];

    const int tid = threadIdx.x;
    const int wid = tid >> 5;
    const int lid = tid & 31;
    const int g   = lid >> 2;   // 0..7
    const int t   = lid & 3;    // 0..3

    const int n     = blockIdx.z;
    const int obase = blockIdx.x * BN;
    const int mbase = blockIdx.y * BM;

    // warp grid 2 (M) x 4 (N): warp tile 64 x 32
    const int wm0 = (wid & 1) * 64;
    const int wn0 = (wid >> 1) * 32;

    const float* xb = x + (size_t)mbase * XSTR + (size_t)n * D_IN;
    const float* wb = w + (size_t)n * WSTR + obase;

    const int a_off = (wm0 + g) * ASTR + t;
    const int b_off = t * BSTR + wn0 + g;

    float acc[4][4][4];
    #pragma unroll
    for (int mt = 0; mt < 4; mt++)
        #pragma unroll
        for (int nt = 0; nt < 4; nt++)
            #pragma unroll
            for (int q = 0; q < 4; q++)
                acc[mt][nt][q] = 0.0f;

    // ---- Prologue: chunks 0 and 1 in flight ----
    prefetch_stage(sm,         xb, wb, 0,  tid);
    prefetch_stage(sm + STAGE, xb, wb, BK, tid);
    cp_wait<1>();               // chunk 0 landed
    __syncthreads();

    uint32_t fa[2][4][4];
    uint32_t fb[2][4][2];
    load_frags(fa[0], fb[0], sm, sm + A_ELE, a_off, b_off, 0);

    for (int it = 0; it < KITERS; ++it) {
        // Prefetch chunk it+2 into stage (it+2)%3 (buffer freed by the
        // __syncthreads at end of iter it-1).
        if (it + 2 < KITERS)
            prefetch_stage(sm + ((it + 2) % NSTAGE) * STAGE, xb, wb, (it + 2) * BK, tid);
        else
            cp_commit();        // keep group numbering

        const float* As = sm + (it % NSTAGE) * STAGE;
        const float* Bs = As + A_ELE;

        #pragma unroll
        for (int ks = 0; ks < 4; ks++) {
            const int cur = ks & 1;
            const int nxt = cur ^ 1;
            if (ks < 3)
                load_frags(fa[nxt], fb[nxt], As, Bs, a_off, b_off, (ks + 1) * 8);
            #pragma unroll
            for (int mt = 0; mt < 4; mt++)
                #pragma unroll
                for (int nt = 0; nt < 4; nt++)
                    mma_tf32(acc[mt][nt], fa[cur][mt], fb[cur][nt]);
        }

        cp_wait<1>();            // chunk it+1 landed
        __syncthreads();         // publish it+1; retire reads of stage it

        if (it + 1 < KITERS) {
            const float* As2 = sm + ((it + 1) % NSTAGE) * STAGE;
            load_frags(fa[0], fb[0], As2, As2 + A_ELE, a_off, b_off, 0);
        }
    }

    // ---- Epilogue: bias + store ----
    const float* brow = bias + (size_t)n * D_OUT + obase;
    #pragma unroll
    for (int mt = 0; mt < 4; mt++) {
        const int r0 = mbase + wm0 + 16 * mt + g;
        float* o0 = out + (size_t)r0 * XSTR + (size_t)n * D_OUT + obase;
        float* o1 = o0 + (size_t)8 * XSTR;
        #pragma unroll
        for (int nt = 0; nt < 4; nt++) {
            const int col = wn0 + 8 * nt + 2 * t;
            float2 bv = *(const float2*)(brow + col);
            float2 v0, v1;
            v0.x = acc[mt][nt][0] + bv.x;
            v0.y = acc[mt][nt][1] + bv.y;
            v1.x = acc[mt][nt][2] + bv.x;
            v1.y = acc[mt][nt][3] + bv.y;
            *(float2*)(o0 + col) = v0;
            *(float2*)(o1 + col) = v1;
        }
    }
}

extern "C" void kernel_launch(void* const* d_in, const int* in_sizes, int n_in,
                              void* d_out, int out_size)
{
    const float* x    = (const float*)d_in[0];
    const float* w    = (const float*)d_in[1];
    const float* bias = (const float*)d_in[2];
    float* out        = (float*)d_out;

    cudaFuncSetAttribute(nlinear_mma_kernel,
                         cudaFuncAttributeMaxDynamicSharedMemorySize, SMEM_BYTES);

    dim3 grid(D_OUT / BN, BATCH / BM, N_POS);   // (4, 2, 128)
    dim3 block(256);
    nlinear_mma_kernel<<<grid, block, SMEM_BYTES>>>(x, w, bias, out);
}

// round 8
// speedup vs baseline: 1.8574x; 1.3580x over previous
#include <cuda_runtime.h>
#include <cstdint>

// NLinear via mma.sync tf32 (base sm_100 target).
// R8: R3 skeleton verbatim (2-stage cp.async, occ 2, per-ks scalar LDS+CVT)
// with exactly ONE change: BSTR 132 -> 136 so B fragment loads are
// bank-conflict-free (bank = 8t+g, all 32 lanes distinct).
// out[b,n,o] = sum_i x[b,n,i]*W[n,i,o] + bias[n,o]

static constexpr int N_POS = 128;
static constexpr int D_IN  = 512;
static constexpr int D_OUT = 512;
static constexpr int BATCH = 256;
static constexpr int XSTR  = N_POS * D_IN;   // 65536: batch-row stride in x/out
static constexpr int WSTR  = D_IN * D_OUT;   // 262144

static constexpr int BM = 128;
static constexpr int BN = 128;
static constexpr int BK = 32;
static constexpr int KITERS = D_IN / BK;     // 16

static constexpr int ASTR = 36;              // A bank = 4g+t (all 32 distinct)
static constexpr int BSTR = 136;             // B bank = 8t+g (all 32 distinct)
static constexpr int A_ELEMS = BM * ASTR;    // 4608
static constexpr int B_ELEMS = BK * BSTR;    // 4352
static constexpr int STAGE   = A_ELEMS + B_ELEMS;  // 8960 floats
static constexpr int SMEM_BYTES = 2 * STAGE * 4;   // 71680

__device__ __forceinline__ void cp16(float* dst_smem, const float* src) {
    uint32_t d = (uint32_t)__cvta_generic_to_shared(dst_smem);
    asm volatile("cp.async.cg.shared.global [%0], [%1], 16;" :: "r"(d), "l"(src));
}
__device__ __forceinline__ void cp_commit() {
    asm volatile("cp.async.commit_group;" ::: "memory");
}
template <int N>
__device__ __forceinline__ void cp_wait() {
    asm volatile("cp.async.wait_group %0;" :: "n"(N) : "memory");
}
__device__ __forceinline__ uint32_t f2tf32(float f) {
    uint32_t r;
    asm("cvt.rna.tf32.f32 %0, %1;" : "=r"(r) : "f"(f));
    return r;
}
__device__ __forceinline__ void mma_tf32(float c[4],
                                         const uint32_t a[4],
                                         const uint32_t b[2]) {
    asm volatile(
        "mma.sync.aligned.m16n8k8.row.col.f32.tf32.tf32.f32 "
        "{%0,%1,%2,%3}, {%4,%5,%6,%7}, {%8,%9}, {%0,%1,%2,%3};"
        : "+f"(c[0]), "+f"(c[1]), "+f"(c[2]), "+f"(c[3])
        : "r"(a[0]), "r"(a[1]), "r"(a[2]), "r"(a[3]), "r"(b[0]), "r"(b[1]));
}

__device__ __forceinline__ void prefetch_stage(float* sm, int stage,
                                               const float* xb, const float* wb,
                                               int k0, int tid)
{
    float* As = sm + stage * STAGE;
    float* Bs = As + A_ELEMS;
    // A tile: 128 rows x 32 floats (128B/row) = 1024 x 16B chunks
    #pragma unroll
    for (int j = 0; j < 4; j++) {
        int c  = tid + j * 256;
        int m  = c >> 3;
        int kc = c & 7;
        cp16(As + m * ASTR + kc * 4, xb + (size_t)m * XSTR + k0 + kc * 4);
    }
    // B tile: 32 rows x 128 floats (512B/row) = 1024 x 16B chunks
    #pragma unroll
    for (int j = 0; j < 4; j++) {
        int c  = tid + j * 256;
        int kr = c >> 5;
        int nc = c & 31;
        cp16(Bs + kr * BSTR + nc * 4, wb + (size_t)(k0 + kr) * D_OUT + nc * 4);
    }
    cp_commit();
}

__global__ __launch_bounds__(256, 2)
void nlinear_mma_kernel(const float* __restrict__ x,
                        const float* __restrict__ w,
                        const float* __restrict__ bias,
                        float* __restrict__ out)
{
    extern __shared__ float sm[];

    const int tid = threadIdx.x;
    const int wid = tid >> 5;
    const int lid = tid & 31;
    const int g   = lid >> 2;   // group id (row within 8)
    const int t   = lid & 3;    // thread-in-group

    const int n     = blockIdx.z;
    const int obase = blockIdx.x * BN;
    const int mbase = blockIdx.y * BM;

    // warp grid 2 (M) x 4 (N): warp tile 64 x 32
    const int wm0 = (wid & 1) * 64;
    const int wn0 = (wid >> 1) * 32;

    const float* xb = x + (size_t)mbase * XSTR + (size_t)n * D_IN;
    const float* wb = w + (size_t)n * WSTR + obase;

    float acc[4][4][4];
    #pragma unroll
    for (int mt = 0; mt < 4; mt++)
        #pragma unroll
        for (int nt = 0; nt < 4; nt++)
            #pragma unroll
            for (int q = 0; q < 4; q++)
                acc[mt][nt][q] = 0.0f;

    prefetch_stage(sm, 0, xb, wb, 0, tid);

    for (int it = 0; it < KITERS; ++it) {
        if (it + 1 < KITERS) {
            prefetch_stage(sm, (it + 1) & 1, xb, wb, (it + 1) * BK, tid);
            cp_wait<1>();
        } else {
            cp_wait<0>();
        }
        __syncthreads();

        const float* As = sm + (it & 1) * STAGE;
        const float* Bs = As + A_ELEMS;

        #pragma unroll
        for (int ks = 0; ks < 4; ks++) {
            const int kk = ks * 8;
            uint32_t a[4][4];
            uint32_t b[4][2];
            #pragma unroll
            for (int mt = 0; mt < 4; mt++) {
                const float* ap = As + (wm0 + 16 * mt + g) * ASTR + kk + t;
                a[mt][0] = f2tf32(ap[0]);
                a[mt][1] = f2tf32(ap[8 * ASTR]);
                a[mt][2] = f2tf32(ap[4]);
                a[mt][3] = f2tf32(ap[8 * ASTR + 4]);
            }
            #pragma unroll
            for (int nt = 0; nt < 4; nt++) {
                const float* bp = Bs + (kk + t) * BSTR + wn0 + 8 * nt + g;
                b[nt][0] = f2tf32(bp[0]);
                b[nt][1] = f2tf32(bp[4 * BSTR]);
            }
            #pragma unroll
            for (int mt = 0; mt < 4; mt++)
                #pragma unroll
                for (int nt = 0; nt < 4; nt++)
                    mma_tf32(acc[mt][nt], a[mt], b[nt]);
        }
        __syncthreads();
    }

    // ---- Epilogue: bias + store ----
    const float* brow = bias + (size_t)n * D_OUT + obase;
    #pragma unroll
    for (int mt = 0; mt < 4; mt++) {
        const int r0 = mbase + wm0 + 16 * mt + g;
        float* o0 = out + (size_t)r0 * XSTR + (size_t)n * D_OUT + obase;
        float* o1 = o0 + (size_t)8 * XSTR;
        #pragma unroll
        for (int nt = 0; nt < 4; nt++) {
            const int col = wn0 + 8 * nt + 2 * t;
            float2 bv = *(const float2*)(brow + col);
            float2 v0, v1;
            v0.x = acc[mt][nt][0] + bv.x;
            v0.y = acc[mt][nt][1] + bv.y;
            v1.x = acc[mt][nt][2] + bv.x;
            v1.y = acc[mt][nt][3] + bv.y;
            *(float2*)(o0 + col) = v0;
            *(float2*)(o1 + col) = v1;
        }
    }
}

extern "C" void kernel_launch(void* const* d_in, const int* in_sizes, int n_in,
                              void* d_out, int out_size)
{
    const float* x    = (const float*)d_in[0];
    const float* w    = (const float*)d_in[1];
    const float* bias = (const float*)d_in[2];
    float* out        = (float*)d_out;

    cudaFuncSetAttribute(nlinear_mma_kernel,
                         cudaFuncAttributeMaxDynamicSharedMemorySize, SMEM_BYTES);

    dim3 grid(D_OUT / BN, BATCH / BM, N_POS);   // (4, 2, 128)
    dim3 block(256);
    nlinear_mma_kernel<<<grid, block, SMEM_BYTES>>>(x, w, bias, out);
}

// round 9
// speedup vs baseline: 1.9144x; 1.0307x over previous
#include <cuda_runtime.h>
#include <cstdint>

// NLinear via mma.sync tf32 (base sm_100 target).
// R9: R8 + ldmatrix.m8n8.x4.b16 for A fragments (4 ldmatrix replace 16 LDS.32
// per thread per k8-step; conflict-free with ASTR=36). B path unchanged
// (BSTR=136, conflict-free scalar LDS). Math bit-identical to R8.
// out[b,n,o] = sum_i x[b,n,i]*W[n,i,o] + bias[n,o]

static constexpr int N_POS = 128;
static constexpr int D_IN  = 512;
static constexpr int D_OUT = 512;
static constexpr int BATCH = 256;
static constexpr int XSTR  = N_POS * D_IN;   // 65536: batch-row stride in x/out
static constexpr int WSTR  = D_IN * D_OUT;   // 262144

static constexpr int BM = 128;
static constexpr int BN = 128;
static constexpr int BK = 32;
static constexpr int KITERS = D_IN / BK;     // 16

static constexpr int ASTR = 36;              // A: ldmatrix rows stride 144B -> all 32 banks
static constexpr int BSTR = 136;             // B: bank = 8t+g (all 32 distinct)
static constexpr int A_ELEMS = BM * ASTR;    // 4608
static constexpr int B_ELEMS = BK * BSTR;    // 4352
static constexpr int STAGE   = A_ELEMS + B_ELEMS;  // 8960 floats
static constexpr int SMEM_BYTES = 2 * STAGE * 4;   // 71680

__device__ __forceinline__ void cp16(float* dst_smem, const float* src) {
    uint32_t d = (uint32_t)__cvta_generic_to_shared(dst_smem);
    asm volatile("cp.async.cg.shared.global [%0], [%1], 16;" :: "r"(d), "l"(src));
}
__device__ __forceinline__ void cp_commit() {
    asm volatile("cp.async.commit_group;" ::: "memory");
}
template <int N>
__device__ __forceinline__ void cp_wait() {
    asm volatile("cp.async.wait_group %0;" :: "n"(N) : "memory");
}
__device__ __forceinline__ uint32_t f2tf32(float f) {
    uint32_t r;
    asm("cvt.rna.tf32.f32 %0, %1;" : "=r"(r) : "f"(f));
    return r;
}
__device__ __forceinline__ uint32_t f2tf32_u(uint32_t u) {
    return f2tf32(__uint_as_float(u));
}
__device__ __forceinline__ void ldmatrix_x4(uint32_t& r0, uint32_t& r1,
                                            uint32_t& r2, uint32_t& r3,
                                            uint32_t smem_addr) {
    asm volatile("ldmatrix.sync.aligned.m8n8.x4.shared.b16 {%0,%1,%2,%3}, [%4];"
                 : "=r"(r0), "=r"(r1), "=r"(r2), "=r"(r3)
                 : "r"(smem_addr));
}
__device__ __forceinline__ void mma_tf32(float c[4],
                                         const uint32_t a[4],
                                         const uint32_t b[2]) {
    asm volatile(
        "mma.sync.aligned.m16n8k8.row.col.f32.tf32.tf32.f32 "
        "{%0,%1,%2,%3}, {%4,%5,%6,%7}, {%8,%9}, {%0,%1,%2,%3};"
        : "+f"(c[0]), "+f"(c[1]), "+f"(c[2]), "+f"(c[3])
        : "r"(a[0]), "r"(a[1]), "r"(a[2]), "r"(a[3]), "r"(b[0]), "r"(b[1]));
}

__device__ __forceinline__ void prefetch_stage(float* sm, int stage,
                                               const float* xb, const float* wb,
                                               int k0, int tid)
{
    float* As = sm + stage * STAGE;
    float* Bs = As + A_ELEMS;
    // A tile: 128 rows x 32 floats (128B/row) = 1024 x 16B chunks
    #pragma unroll
    for (int j = 0; j < 4; j++) {
        int c  = tid + j * 256;
        int m  = c >> 3;
        int kc = c & 7;
        cp16(As + m * ASTR + kc * 4, xb + (size_t)m * XSTR + k0 + kc * 4);
    }
    // B tile: 32 rows x 128 floats (512B/row) = 1024 x 16B chunks
    #pragma unroll
    for (int j = 0; j < 4; j++) {
        int c  = tid + j * 256;
        int kr = c >> 5;
        int nc = c & 31;
        cp16(Bs + kr * BSTR + nc * 4, wb + (size_t)(k0 + kr) * D_OUT + nc * 4);
    }
    cp_commit();
}

__global__ __launch_bounds__(256, 2)
void nlinear_mma_kernel(const float* __restrict__ x,
                        const float* __restrict__ w,
                        const float* __restrict__ bias,
                        float* __restrict__ out)
{
    extern __shared__ float sm[];

    const int tid = threadIdx.x;
    const int wid = tid >> 5;
    const int lid = tid & 31;
    const int g   = lid >> 2;   // group id (row within 8)
    const int t   = lid & 3;    // thread-in-group

    const int n     = blockIdx.z;
    const int obase = blockIdx.x * BN;
    const int mbase = blockIdx.y * BM;

    // warp grid 2 (M) x 4 (N): warp tile 64 x 32
    const int wm0 = (wid & 1) * 64;
    const int wn0 = (wid >> 1) * 32;

    const float* xb = x + (size_t)mbase * XSTR + (size_t)n * D_IN;
    const float* wb = w + (size_t)n * WSTR + obase;

    // ldmatrix per-lane byte offset within the A tile:
    // row = wm0 + (lid & 15), col add = (lid>>4)*4 tf32 columns
    const uint32_t smem_u32 = (uint32_t)__cvta_generic_to_shared(sm);
    const uint32_t a_lm_off =
        (uint32_t)(((wm0 + (lid & 15)) * ASTR + (lid >> 4) * 4) * 4);

    float acc[4][4][4];
    #pragma unroll
    for (int mt = 0; mt < 4; mt++)
        #pragma unroll
        for (int nt = 0; nt < 4; nt++)
            #pragma unroll
            for (int q = 0; q < 4; q++)
                acc[mt][nt][q] = 0.0f;

    prefetch_stage(sm, 0, xb, wb, 0, tid);

    for (int it = 0; it < KITERS; ++it) {
        if (it + 1 < KITERS) {
            prefetch_stage(sm, (it + 1) & 1, xb, wb, (it + 1) * BK, tid);
            cp_wait<1>();
        } else {
            cp_wait<0>();
        }
        __syncthreads();

        const uint32_t As_u32 = smem_u32 + (uint32_t)((it & 1) * STAGE * 4);
        const float*   Bs     = sm + (it & 1) * STAGE + A_ELEMS;

        #pragma unroll
        for (int ks = 0; ks < 4; ks++) {
            const int kk = ks * 8;
            uint32_t a[4][4];
            uint32_t b[4][2];
            #pragma unroll
            for (int mt = 0; mt < 4; mt++) {
                uint32_t r0, r1, r2, r3;
                ldmatrix_x4(r0, r1, r2, r3,
                            As_u32 + a_lm_off + (uint32_t)((mt * 16 * ASTR + kk) * 4));
                a[mt][0] = f2tf32_u(r0);   // (g,   t)
                a[mt][1] = f2tf32_u(r1);   // (g+8, t)
                a[mt][2] = f2tf32_u(r2);   // (g,   t+4)
                a[mt][3] = f2tf32_u(r3);   // (g+8, t+4)
            }
            #pragma unroll
            for (int nt = 0; nt < 4; nt++) {
                const float* bp = Bs + (kk + t) * BSTR + wn0 + 8 * nt + g;
                b[nt][0] = f2tf32(bp[0]);
                b[nt][1] = f2tf32(bp[4 * BSTR]);
            }
            #pragma unroll
            for (int mt = 0; mt < 4; mt++)
                #pragma unroll
                for (int nt = 0; nt < 4; nt++)
                    mma_tf32(acc[mt][nt], a[mt], b[nt]);
        }
        __syncthreads();
    }

    // ---- Epilogue: bias + store ----
    const float* brow = bias + (size_t)n * D_OUT + obase;
    #pragma unroll
    for (int mt = 0; mt < 4; mt++) {
        const int r0 = mbase + wm0 + 16 * mt + g;
        float* o0 = out + (size_t)r0 * XSTR + (size_t)n * D_OUT + obase;
        float* o1 = o0 + (size_t)8 * XSTR;
        #pragma unroll
        for (int nt = 0; nt < 4; nt++) {
            const int col = wn0 + 8 * nt + 2 * t;
            float2 bv = *(const float2*)(brow + col);
            float2 v0, v1;
            v0.x = acc[mt][nt][0] + bv.x;
            v0.y = acc[mt][nt][1] + bv.y;
            v1.x = acc[mt][nt][2] + bv.x;
            v1.y = acc[mt][nt][3] + bv.y;
            *(float2*)(o0 + col) = v0;
            *(float2*)(o1 + col) = v1;
        }
    }
}

extern "C" void kernel_launch(void* const* d_in, const int* in_sizes, int n_in,
                              void* d_out, int out_size)
{
    const float* x    = (const float*)d_in[0];
    const float* w    = (const float*)d_in[1];
    const float* bias = (const float*)d_in[2];
    float* out        = (float*)d_out;

    cudaFuncSetAttribute(nlinear_mma_kernel,
                         cudaFuncAttributeMaxDynamicSharedMemorySize, SMEM_BYTES);

    dim3 grid(D_OUT / BN, BATCH / BM, N_POS);   // (4, 2, 128)
    dim3 block(256);
    nlinear_mma_kernel<<<grid, block, SMEM_BYTES>>>(x, w, bias, out);
}